// round 10
// baseline (speedup 1.0000x reference)
#include <cuda_runtime.h>
#include <cuda_bf16.h>
#include <math.h>
#include <stdint.h>

typedef unsigned long long u64;
typedef unsigned int u32;

#define BATCH 8
#define CIN 1024
#define CMID 512
#define HH 50
#define WW 50
#define HW 2500
#define NA 9
#define NANCH 22500
#define SEG 32768
#define PRE_N 2000
#define POST_N 100

__device__ float   g_t[(size_t)BATCH * HW * CMID];
__device__ float   g_boxes[(size_t)BATCH * NANCH * 4];
__device__ u64     g_keys[(size_t)BATCH * SEG];
__device__ float   g_topboxes[(size_t)BATCH * PRE_N * 4];
__device__ float   g_topscores[(size_t)BATCH * PRE_N];
__device__ u64     g_mask[(size_t)BATCH * PRE_N * 32];
__device__ u64     g_keep[BATCH * 32];

__device__ __forceinline__ u32 ordf(float f) {
    u32 b = __float_as_uint(f);
    return (b & 0x80000000u) ? ~b : (b | 0x80000000u);
}
__device__ __forceinline__ float unordf(u32 o) {
    u32 b = (o & 0x80000000u) ? (o ^ 0x80000000u) : ~o;
    return __uint_as_float(b);
}
__device__ __forceinline__ void fma2(u64& c, u64 a, u64 b) {
    asm("fma.rn.f32x2 %0, %1, %2, %0;" : "+l"(c) : "l"(a), "l"(b));
}
__device__ __forceinline__ void unpack2(u64 v, float& lo, float& hi) {
    asm("mov.b64 {%0, %1}, %2;" : "=f"(lo), "=f"(hi) : "l"(v));
}
__device__ __forceinline__ u32 smem_u32(const void* p) {
    u32 a;
    asm("{ .reg .u64 t; cvta.to.shared.u64 t, %1; cvt.u32.u64 %0, t; }" : "=r"(a) : "l"(p));
    return a;
}

// ---------------- conv 3x3 (1024->512) + bias + relu, implicit GEMM, fp32x2 ----------------
// TM=64, TN=128, TK=8; microtile 4 rows x 8 cols (4 col-pairs) per thread.
// A is stored PRE-DUPLICATED in smem (u64 = {v,v}); B stored as col-pairs (u64 = {c,c+1}).
// Per-output k-accumulation order identical to R9 -> bit-identical result.
#define TM 64
#define TN 128
#define TK 8
__global__ __launch_bounds__(256) void conv_kernel(
    const float* __restrict__ feat, const float* __restrict__ W1,
    const float* __restrict__ b1, float* __restrict__ out)
{
    __shared__ u64 As2[TK][TM];        // dup'd A values: 4KB
    __shared__ u64 Bs2[TK][TN / 2];    // col-pair-packed B: 4KB

    const int m0 = blockIdx.x * TM;
    const int o0 = blockIdx.y * TN;
    const int b  = blockIdx.z;
    const int tid = threadIdx.x;
    const int tx = tid & 15;   // m micro-tile: rows tx*4 .. tx*4+3
    const int ty = tid >> 4;   // n micro-tile: col-pairs ty*4 .. ty*4+3 (cols ty*8..ty*8+7)

    const float* fb = feat + (size_t)b * CIN * HW;

    u64 acc2[4][4];
#pragma unroll
    for (int i = 0; i < 4; i++)
#pragma unroll
        for (int j = 0; j < 4; j++) acc2[i][j] = 0ull;

    const u32 a2 = smem_u32(&As2[0][0]);
    const u32 b2s = smem_u32(&Bs2[0][0]);

    for (int k0 = 0; k0 < CIN * 9; k0 += TK) {
        // A tile (im2col on the fly): 512 values, 2 per thread, stored duplicated
#pragma unroll
        for (int it = 0; it < 2; it++) {
            int e = tid + it * 256;
            int kk = e >> 6, mm = e & 63;
            int k = k0 + kk;
            int c = k / 9, tap = k - c * 9;
            int dy = tap / 3 - 1, dx = tap - (tap / 3) * 3 - 1;
            int m = m0 + mm;
            int y = m / WW, x = m - y * WW;
            int yy = y + dy, xx = x + dx;
            float v = 0.f;
            if (m < HW && (unsigned)yy < HH && (unsigned)xx < WW)
                v = fb[(size_t)c * HW + yy * WW + xx];
            u64 dv;
            asm("mov.b64 %0, {%1, %1};" : "=l"(dv) : "f"(v));
            As2[kk][mm] = dv;
        }
        // B tile: coalesced float4 per thread along k, scatter into col-pair layout
        {
            int oo = tid >> 1;               // 0..127 output col
            int kq = (tid & 1) * 4;
            float4 w4 = *reinterpret_cast<const float4*>(&W1[(size_t)(o0 + oo) * (CIN * 9) + k0 + kq]);
            u32 base = b2s + (u32)(oo >> 1) * 8u + (u32)(oo & 1) * 4u;
            asm volatile("st.shared.f32 [%0], %1;" :: "r"(base + (kq + 0) * (TN / 2) * 8), "f"(w4.x));
            asm volatile("st.shared.f32 [%0], %1;" :: "r"(base + (kq + 1) * (TN / 2) * 8), "f"(w4.y));
            asm volatile("st.shared.f32 [%0], %1;" :: "r"(base + (kq + 2) * (TN / 2) * 8), "f"(w4.z));
            asm volatile("st.shared.f32 [%0], %1;" :: "r"(base + (kq + 3) * (TN / 2) * 8), "f"(w4.w));
        }
        __syncthreads();

#pragma unroll
        for (int kk = 0; kk < TK; kk++) {
            u64 ad[4], bp[4];
            u32 aaddr = a2 + (u32)(kk * TM + tx * 4) * 8u;
            asm("ld.shared.v2.b64 {%0, %1}, [%2];" : "=l"(ad[0]), "=l"(ad[1]) : "r"(aaddr));
            asm("ld.shared.v2.b64 {%0, %1}, [%2];" : "=l"(ad[2]), "=l"(ad[3]) : "r"(aaddr + 16u));
            u32 baddr = b2s + (u32)(kk * (TN / 2) + ty * 4) * 8u;
            asm("ld.shared.v2.b64 {%0, %1}, [%2];" : "=l"(bp[0]), "=l"(bp[1]) : "r"(baddr));
            asm("ld.shared.v2.b64 {%0, %1}, [%2];" : "=l"(bp[2]), "=l"(bp[3]) : "r"(baddr + 16u));
#pragma unroll
            for (int i = 0; i < 4; i++)
#pragma unroll
                for (int j = 0; j < 4; j++) fma2(acc2[i][j], ad[i], bp[j]);
        }
        __syncthreads();
    }

#pragma unroll
    for (int i = 0; i < 4; i++) {
        int m = m0 + tx * 4 + i;
        if (m >= HW) continue;
        float* row = out + ((size_t)b * HW + m) * CMID + o0 + ty * 8;
#pragma unroll
        for (int j = 0; j < 4; j++) {
            float lo, hi;
            unpack2(acc2[i][j], lo, hi);
            float v0 = lo + b1[o0 + ty * 8 + j * 2];
            float v1 = hi + b1[o0 + ty * 8 + j * 2 + 1];
            float2 o;
            o.x = v0 > 0.f ? v0 : 0.f;
            o.y = v1 > 0.f ? v1 : 0.f;
            *reinterpret_cast<float2*>(row + j * 2) = o;
        }
    }
}

// ---------------- head: 45-output GEMV + decode + score + key ----------------
__global__ __launch_bounds__(64) void head_kernel(
    const float* __restrict__ t, const float* __restrict__ W2, const float* __restrict__ b2,
    const float* __restrict__ W3, const float* __restrict__ b3,
    float* __restrict__ boxes_all, u64* __restrict__ keys)
{
    const int pos = blockIdx.x;
    const int b = pos / HW;
    const int m = pos - b * HW;
    const int y = m / WW, x = m - y * WW;
    const int tid = threadIdx.x;

    __shared__ float tv[CMID];
    __shared__ float outv[48];

    const float* trow = t + (size_t)pos * CMID;
#pragma unroll
    for (int i = 0; i < 2; i++)
        reinterpret_cast<float4*>(tv)[tid + i * 64] =
            reinterpret_cast<const float4*>(trow)[tid + i * 64];
    __syncthreads();

    if (tid < 45) {
        const float* wr;
        float bias;
        if (tid < 36) { wr = W2 + (size_t)tid * CMID; bias = b2[tid]; }
        else          { wr = W3 + (size_t)(tid - 36) * CMID; bias = b3[tid - 36]; }
        float s0 = 0.f, s1 = 0.f, s2 = 0.f, s3 = 0.f;
        for (int j = 0; j < CMID; j += 4) {
            float4 tvv = *reinterpret_cast<const float4*>(&tv[j]);
            float4 wv = *reinterpret_cast<const float4*>(&wr[j]);
            s0 += tvv.x * wv.x; s1 += tvv.y * wv.y;
            s2 += tvv.z * wv.z; s3 += tvv.w * wv.w;
        }
        outv[tid] = ((s0 + s1) + (s2 + s3)) + bias;
    }
    __syncthreads();

    if (tid < NA) {
        const int a = tid;
        const double areas[3] = {16384.0, 65536.0, 262144.0};
        const double ratios[3] = {0.5, 1.0, 2.0};
        int ia = a / 3, ir = a - ia * 3;
        float w = (float)sqrt(areas[ia] * ratios[ir]);
        float h = (float)sqrt(areas[ia] / ratios[ir]);

        float tx_ = outv[a * 4 + 0];
        float ty_ = outv[a * 4 + 1];
        float clip = (float)log(62.5);
        float tw_ = fminf(outv[a * 4 + 2], clip);
        float th_ = fminf(outv[a * 4 + 3], clip);
        float logit = outv[36 + a];

        float cx = ((float)x + 0.5f) * 32.f;
        float cy = ((float)y + 0.5f) * 32.f;
        float x1 = cx - w * 0.5f, x2 = cx + w * 0.5f;
        float y1 = cy - h * 0.5f, y2 = cy + h * 0.5f;
        float wa = x2 - x1, ha = y2 - y1;
        float cxa = x1 + 0.5f * wa, cya = y1 + 0.5f * ha;

        float px = tx_ * wa + cxa;
        float py = ty_ * ha + cya;
        float pw = expf(tw_) * wa;
        float ph = expf(th_) * ha;

        float bx1 = fminf(fmaxf(px - pw * 0.5f, 0.f), 1600.f);
        float by1 = fminf(fmaxf(py - ph * 0.5f, 0.f), 1600.f);
        float bx2 = fminf(fmaxf(px + pw * 0.5f, 0.f), 1600.f);
        float by2 = fminf(fmaxf(py + ph * 0.5f, 0.f), 1600.f);

        float bw = bx2 - bx1, bh = by2 - by1;
        float score = 1.f / (1.f + expf(-logit));
        bool valid = (score >= 0.1f) && (bw > 16.f) && (bh > 16.f);
        float ms = valid ? score : -1.0f;

        int idx = m * NA + a;
        size_t bi = (size_t)b * NANCH + idx;
        boxes_all[bi * 4 + 0] = bx1;
        boxes_all[bi * 4 + 1] = by1;
        boxes_all[bi * 4 + 2] = bx2;
        boxes_all[bi * 4 + 3] = by2;
        keys[(size_t)b * SEG + idx] = ((u64)(~ordf(ms)) << 32) | (u32)idx;
    }
}

// ---------------- bitonic sort ----------------
__global__ __launch_bounds__(1024) void bsortA(u64* __restrict__ keys)
{
    __shared__ u64 s[4096];
    const int cb = blockIdx.x * 4096;
    const int segb = cb & (SEG - 1);
    const int tid = threadIdx.x;
#pragma unroll
    for (int i = 0; i < 4; i++) s[tid + i * 1024] = keys[cb + tid + i * 1024];
    __syncthreads();
    for (int size = 2; size <= 4096; size <<= 1) {
        for (int stride = size >> 1; stride >= 1; stride >>= 1) {
#pragma unroll 1
            for (int t = tid; t < 2048; t += 1024) {
                int l = ((t & ~(stride - 1)) << 1) | (t & (stride - 1));
                int r = l | stride;
                bool up = (((l + segb) & size) == 0);
                u64 a = s[l], bk = s[r];
                if ((a > bk) == up) { s[l] = bk; s[r] = a; }
            }
            __syncthreads();
        }
    }
#pragma unroll
    for (int i = 0; i < 4; i++) keys[cb + tid + i * 1024] = s[tid + i * 1024];
}

__global__ __launch_bounds__(256) void bsortG(u64* __restrict__ keys, int size, int stride)
{
    int t = blockIdx.x * blockDim.x + threadIdx.x;
    int l = ((t & ~(stride - 1)) << 1) | (t & (stride - 1));
    int r = l | stride;
    bool up = (((l & (SEG - 1)) & size) == 0);
    u64 a = keys[l], bk = keys[r];
    if ((a > bk) == up) { keys[l] = bk; keys[r] = a; }
}

__global__ __launch_bounds__(1024) void bsortF(u64* __restrict__ keys, int size)
{
    __shared__ u64 s[4096];
    const int cb = blockIdx.x * 4096;
    const int segb = cb & (SEG - 1);
    const int tid = threadIdx.x;
#pragma unroll
    for (int i = 0; i < 4; i++) s[tid + i * 1024] = keys[cb + tid + i * 1024];
    __syncthreads();
    const bool up = ((segb & size) == 0);
    for (int stride = 2048; stride >= 1; stride >>= 1) {
#pragma unroll 1
        for (int t = tid; t < 2048; t += 1024) {
            int l = ((t & ~(stride - 1)) << 1) | (t & (stride - 1));
            int r = l | stride;
            u64 a = s[l], bk = s[r];
            if ((a > bk) == up) { s[l] = bk; s[r] = a; }
        }
        __syncthreads();
    }
#pragma unroll
    for (int i = 0; i < 4; i++) keys[cb + tid + i * 1024] = s[tid + i * 1024];
}

// ---------------- gather top-2000 ----------------
__global__ __launch_bounds__(256) void gather_kernel(
    const u64* __restrict__ keys, const float* __restrict__ boxes_all,
    float* __restrict__ topboxes, float* __restrict__ topscores)
{
    int t = blockIdx.x * blockDim.x + threadIdx.x;
    if (t >= BATCH * PRE_N) return;
    int seg = t / PRE_N, r = t - seg * PRE_N;
    u64 key = keys[(size_t)seg * SEG + r];
    u32 idx = (u32)(key & 0xFFFFFFFFu);
    topscores[t] = unordf(~(u32)(key >> 32));
    float4 bb = *reinterpret_cast<const float4*>(boxes_all + ((size_t)seg * NANCH + idx) * 4);
    *reinterpret_cast<float4*>(topboxes + (size_t)t * 4) = bb;
}

// ---------------- NMS ----------------
__device__ __forceinline__ bool iou_gt(float4 bi, float area_i, float4 bj)
{
    float area_j = (bj.z - bj.x) * (bj.w - bj.y);
    float ltx = fmaxf(bi.x, bj.x), lty = fmaxf(bi.y, bj.y);
    float rbx = fminf(bi.z, bj.z), rby = fminf(bi.w, bj.w);
    float wx = fmaxf(rbx - ltx, 0.f), wy = fmaxf(rby - lty, 0.f);
    float inter = wx * wy;
    return inter / (area_i + area_j - inter + 1e-9f) > 0.7f;
}

__global__ __launch_bounds__(256) void mask_kernel(
    const float* __restrict__ topboxes, u64* __restrict__ masks)
{
    int row = blockIdx.x * 8 + (threadIdx.x >> 5);
    int lane = threadIdx.x & 31;
    int seg = row / PRE_N, i = row - seg * PRE_N;
    const float* B = topboxes + (size_t)seg * PRE_N * 4;
    float4 bi = *reinterpret_cast<const float4*>(B + (size_t)i * 4);
    float area_i = (bi.z - bi.x) * (bi.w - bi.y);
    u64* mrow = masks + (size_t)row * 32;
    for (int w = 0; w < 32; w++) {
        int j0 = w * 64;
        bool p0 = false, p1 = false;
        int j = j0 + lane;
        if (j < PRE_N && j > i)
            p0 = iou_gt(bi, area_i, *reinterpret_cast<const float4*>(B + (size_t)j * 4));
        j = j0 + 32 + lane;
        if (j < PRE_N && j > i)
            p1 = iou_gt(bi, area_i, *reinterpret_cast<const float4*>(B + (size_t)j * 4));
        u32 lo = __ballot_sync(0xFFFFFFFFu, p0);
        u32 hi = __ballot_sync(0xFFFFFFFFu, p1);
        if (lane == 0) mrow[w] = ((u64)hi << 32) | lo;
    }
}

__global__ __launch_bounds__(256) void scan_kernel(
    const float* __restrict__ topscores, const u64* __restrict__ masks, u64* __restrict__ keep)
{
    const int seg = blockIdx.x;
    __shared__ u64 buf[64 * 32];
    const int tid = threadIdx.x;
    const int lane = tid & 31, wid = tid >> 5;

    u64 keepw = 0;
    if (wid == 0) {
        for (int bbit = 0; bbit < 64; bbit++) {
            int i = lane * 64 + bbit;
            if (i < PRE_N && topscores[seg * PRE_N + i] > 0.f) keepw |= 1ULL << bbit;
        }
    }
    const u64* mseg = masks + (size_t)seg * PRE_N * 32;
    for (int c = 0; c < 32; c++) {
        __syncthreads();
        int r0 = c * 64;
        for (int e = tid; e < 64 * 32; e += 256) {
            int rr = e >> 5, wwi = e & 31;
            int row = r0 + rr;
            buf[e] = (row < PRE_N) ? mseg[(size_t)row * 32 + wwi] : 0ULL;
        }
        __syncthreads();
        if (wid == 0) {
            int n = PRE_N - r0; if (n > 64) n = 64;
            for (int r = 0; r < n; r++) {
                u64 kw = __shfl_sync(0xFFFFFFFFu, keepw, c);
                if ((kw >> r) & 1ULL) keepw &= ~buf[r * 32 + lane];
            }
        }
    }
    __syncthreads();
    if (wid == 0) keep[seg * 32 + lane] = keepw;
}

__global__ __launch_bounds__(1024) void post_kernel(
    const float* __restrict__ topscores, const float* __restrict__ topboxes,
    const u64* __restrict__ keepbits, float* __restrict__ out)
{
    const int seg = blockIdx.x;
    __shared__ u64 s[2048];
    const int tid = threadIdx.x;
    for (int i = tid; i < 2048; i += 1024) {
        u64 key;
        if (i < PRE_N) {
            float sc = topscores[seg * PRE_N + i];
            int kept = (int)((keepbits[seg * 32 + (i >> 6)] >> (i & 63)) & 1ULL);
            float ms = kept ? sc : -1.0f;
            key = ((u64)(~ordf(ms)) << 32) | (u32)i;
        } else key = ~0ULL;
        s[i] = key;
    }
    __syncthreads();
    for (int size = 2; size <= 2048; size <<= 1)
        for (int stride = size >> 1; stride >= 1; stride >>= 1) {
            int l = ((tid & ~(stride - 1)) << 1) | (tid & (stride - 1));
            int r = l | stride;
            bool up = ((l & size) == 0);
            u64 a = s[l], bk = s[r];
            if ((a > bk) == up) { s[l] = bk; s[r] = a; }
            __syncthreads();
        }
    if (tid < POST_N) {
        u64 key = s[tid];
        u32 idx = (u32)(key & 0xFFFFFFFFu);
        float sc = unordf(~(u32)(key >> 32));
        float4 bb = *reinterpret_cast<const float4*>(topboxes + ((size_t)seg * PRE_N + idx) * 4);
        float* ob = out + ((size_t)seg * POST_N + tid) * 4;
        ob[0] = bb.x; ob[1] = bb.y; ob[2] = bb.z; ob[3] = bb.w;
        out[BATCH * POST_N * 4 + seg * POST_N + tid] = sc;
    }
}

// ---------------- launch ----------------
extern "C" void kernel_launch(void* const* d_in, const int* in_sizes, int n_in,
                              void* d_out, int out_size)
{
    const float* feat = (const float*)d_in[0];
    const float* W1   = (const float*)d_in[1];
    const float* b1   = (const float*)d_in[2];
    const float* W2   = (const float*)d_in[3];
    const float* b2   = (const float*)d_in[4];
    const float* W3   = (const float*)d_in[5];
    const float* b3   = (const float*)d_in[6];
    float* out = (float*)d_out;

    float *t_ptr, *boxes_ptr, *tb_ptr, *ts_ptr;
    u64 *keys_ptr, *mask_ptr, *keep_ptr;
    cudaGetSymbolAddress((void**)&t_ptr, g_t);
    cudaGetSymbolAddress((void**)&boxes_ptr, g_boxes);
    cudaGetSymbolAddress((void**)&keys_ptr, g_keys);
    cudaGetSymbolAddress((void**)&tb_ptr, g_topboxes);
    cudaGetSymbolAddress((void**)&ts_ptr, g_topscores);
    cudaGetSymbolAddress((void**)&mask_ptr, g_mask);
    cudaGetSymbolAddress((void**)&keep_ptr, g_keep);

    // 1. conv + relu (fp32x2, pre-dup A, fine-grained grid)
    dim3 cgrid((HW + TM - 1) / TM, CMID / TN, BATCH);   // 40 x 4 x 8 = 1280 CTAs
    conv_kernel<<<cgrid, 256>>>(feat, W1, b1, t_ptr);

    // 2. pad keys then head
    cudaMemsetAsync(keys_ptr, 0xFF, (size_t)BATCH * SEG * sizeof(u64));
    head_kernel<<<BATCH * HW, 64>>>(t_ptr, W2, b2, W3, b3, boxes_ptr, keys_ptr);

    // 3. per-segment bitonic sort
    bsortA<<<BATCH * SEG / 4096, 1024>>>(keys_ptr);
    bsortG<<<512, 256>>>(keys_ptr, 8192, 4096);
    bsortF<<<BATCH * SEG / 4096, 1024>>>(keys_ptr, 8192);
    bsortG<<<512, 256>>>(keys_ptr, 16384, 8192);
    bsortG<<<512, 256>>>(keys_ptr, 16384, 4096);
    bsortF<<<BATCH * SEG / 4096, 1024>>>(keys_ptr, 16384);
    bsortG<<<512, 256>>>(keys_ptr, 32768, 16384);
    bsortG<<<512, 256>>>(keys_ptr, 32768, 8192);
    bsortG<<<512, 256>>>(keys_ptr, 32768, 4096);
    bsortF<<<BATCH * SEG / 4096, 1024>>>(keys_ptr, 32768);

    // 4-6. gather, NMS, output
    gather_kernel<<<(BATCH * PRE_N + 255) / 256, 256>>>(keys_ptr, boxes_ptr, tb_ptr, ts_ptr);
    mask_kernel<<<BATCH * PRE_N / 8, 256>>>(tb_ptr, mask_ptr);
    scan_kernel<<<BATCH, 256>>>(ts_ptr, mask_ptr, keep_ptr);
    post_kernel<<<BATCH, 1024>>>(ts_ptr, tb_ptr, keep_ptr, out);
}

// round 11
// speedup vs baseline: 2.6936x; 2.6936x over previous
#include <cuda_runtime.h>
#include <cuda_bf16.h>
#include <math.h>
#include <stdint.h>

typedef unsigned long long u64;
typedef unsigned int u32;

#define BATCH 8
#define CIN 1024
#define CMID 512
#define HH 50
#define WW 50
#define HW 2500
#define NA 9
#define NANCH 22500
#define SEG 32768
#define PRE_N 2000
#define POST_N 100

__device__ float   g_t[(size_t)BATCH * HW * CMID];
__device__ float   g_boxes[(size_t)BATCH * NANCH * 4];
__device__ u64     g_keys[(size_t)BATCH * SEG];
__device__ float   g_topboxes[(size_t)BATCH * PRE_N * 4];
__device__ float   g_topscores[(size_t)BATCH * PRE_N];
__device__ u64     g_mask[(size_t)BATCH * PRE_N * 32];
__device__ u64     g_keep[BATCH * 32];

__device__ __forceinline__ u32 ordf(float f) {
    u32 b = __float_as_uint(f);
    return (b & 0x80000000u) ? ~b : (b | 0x80000000u);
}
__device__ __forceinline__ float unordf(u32 o) {
    u32 b = (o & 0x80000000u) ? (o ^ 0x80000000u) : ~o;
    return __uint_as_float(b);
}
__device__ __forceinline__ void fma2(u64& c, u64 a, u64 b) {
    asm("fma.rn.f32x2 %0, %1, %2, %0;" : "+l"(c) : "l"(a), "l"(b));
}
__device__ __forceinline__ void unpack2(u64 v, float& lo, float& hi) {
    asm("mov.b64 {%0, %1}, %2;" : "=f"(lo), "=f"(hi) : "l"(v));
}
__device__ __forceinline__ u32 smem_u32(const void* p) {
    u32 a;
    asm("{ .reg .u64 t; cvta.to.shared.u64 t, %1; cvt.u32.u64 %0, t; }" : "=r"(a) : "l"(p));
    return a;
}

// ---------------- conv 3x3 (1024->512) + bias + relu, implicit GEMM, fp32x2 ----------------
// TM=128 TN=128 TK=16, micro-tile 8x8, register prefetch of next K-block.
// Per-output k order identical to R1/R9 (ascending k) -> bit-identical conv output.
#define TM 128
#define TN 128
#define TK 16
__global__ __launch_bounds__(256, 2) void conv_kernel(
    const float* __restrict__ feat, const float* __restrict__ W1,
    const float* __restrict__ b1, float* __restrict__ out)
{
    __shared__ float As[TK][TM];   // 8KB
    __shared__ float Bs[TK][TN];   // 8KB

    const int m0 = blockIdx.x * TM;
    const int o0 = blockIdx.y * TN;
    const int b  = blockIdx.z;
    const int tid = threadIdx.x;
    const int tx = tid & 15;   // m micro-tile rows tx*8..tx*8+7
    const int ty = tid >> 4;   // n micro-tile cols ty*8..ty*8+7

    const float* fb = feat + (size_t)b * CIN * HW;

    // per-thread A-loader invariants: 8 chunks (kk, mm)
    int kkA[8], yA[8], xA[8];
    bool mvA[8];
#pragma unroll
    for (int it = 0; it < 8; it++) {
        int e = tid + it * 256;
        kkA[it] = e >> 7;
        int mm = e & 127;
        int m = m0 + mm;
        mvA[it] = m < HW;
        int mc = mvA[it] ? m : 0;
        yA[it] = mc / WW; xA[it] = mc - yA[it] * WW;
    }
    const int mmA_base = tid & 127;  // mm for chunk it: same across it? no: e&127 = (tid + it*256)&127 = tid&127
    // (it*256 & 127 == 0, so mm is constant = tid&127 for all chunks)
    const int ooB = tid >> 1;
    const int kqB = (tid & 1) * 8;
    const float* wrow = W1 + (size_t)(o0 + ooB) * (CIN * 9) + kqB;

    u64 acc2[8][4];
#pragma unroll
    for (int i = 0; i < 8; i++)
#pragma unroll
        for (int j = 0; j < 4; j++) acc2[i][j] = 0ull;

    // prefetch registers
    float pa[8];
    float4 pb0, pb1;

    // prologue: load k0 = 0
#pragma unroll
    for (int it = 0; it < 8; it++) {
        int k = kkA[it];
        int c = k / 9, tap = k - c * 9;
        int yy = yA[it] + tap / 3 - 1, xx = xA[it] + tap % 3 - 1;
        float v = 0.f;
        if (mvA[it] && (unsigned)yy < HH && (unsigned)xx < WW)
            v = fb[(size_t)c * HW + yy * WW + xx];
        pa[it] = v;
    }
    pb0 = *reinterpret_cast<const float4*>(wrow);
    pb1 = *reinterpret_cast<const float4*>(wrow + 4);

    for (int k0 = 0; k0 < CIN * 9; k0 += TK) {
        // store prefetched tile
#pragma unroll
        for (int it = 0; it < 8; it++)
            As[kkA[it]][mmA_base] = pa[it];
        Bs[kqB + 0][ooB] = pb0.x; Bs[kqB + 1][ooB] = pb0.y;
        Bs[kqB + 2][ooB] = pb0.z; Bs[kqB + 3][ooB] = pb0.w;
        Bs[kqB + 4][ooB] = pb1.x; Bs[kqB + 5][ooB] = pb1.y;
        Bs[kqB + 6][ooB] = pb1.z; Bs[kqB + 7][ooB] = pb1.w;
        __syncthreads();

        // prefetch next K-block (hidden under compute below)
        if (k0 + TK < CIN * 9) {
            int kn = k0 + TK;
#pragma unroll
            for (int it = 0; it < 8; it++) {
                int k = kn + kkA[it];
                int c = k / 9, tap = k - c * 9;
                int yy = yA[it] + tap / 3 - 1, xx = xA[it] + tap % 3 - 1;
                float v = 0.f;
                if (mvA[it] && (unsigned)yy < HH && (unsigned)xx < WW)
                    v = fb[(size_t)c * HW + yy * WW + xx];
                pa[it] = v;
            }
            pb0 = *reinterpret_cast<const float4*>(wrow + kn);
            pb1 = *reinterpret_cast<const float4*>(wrow + kn + 4);
        }

        // compute 16 kk steps (same per-output order as before)
#pragma unroll
        for (int kk = 0; kk < TK; kk++) {
            float4 a0 = *reinterpret_cast<const float4*>(&As[kk][tx * 8]);
            float4 a1 = *reinterpret_cast<const float4*>(&As[kk][tx * 8 + 4]);
            u64 ad[8];
            asm("mov.b64 %0, {%1, %1};" : "=l"(ad[0]) : "f"(a0.x));
            asm("mov.b64 %0, {%1, %1};" : "=l"(ad[1]) : "f"(a0.y));
            asm("mov.b64 %0, {%1, %1};" : "=l"(ad[2]) : "f"(a0.z));
            asm("mov.b64 %0, {%1, %1};" : "=l"(ad[3]) : "f"(a0.w));
            asm("mov.b64 %0, {%1, %1};" : "=l"(ad[4]) : "f"(a1.x));
            asm("mov.b64 %0, {%1, %1};" : "=l"(ad[5]) : "f"(a1.y));
            asm("mov.b64 %0, {%1, %1};" : "=l"(ad[6]) : "f"(a1.z));
            asm("mov.b64 %0, {%1, %1};" : "=l"(ad[7]) : "f"(a1.w));
            const u64* brow = reinterpret_cast<const u64*>(&Bs[kk][ty * 8]);
            u64 bp0 = brow[0], bp1 = brow[1], bp2 = brow[2], bp3 = brow[3];
#pragma unroll
            for (int i = 0; i < 8; i++) {
                fma2(acc2[i][0], ad[i], bp0);
                fma2(acc2[i][1], ad[i], bp1);
                fma2(acc2[i][2], ad[i], bp2);
                fma2(acc2[i][3], ad[i], bp3);
            }
        }
        __syncthreads();
    }

#pragma unroll
    for (int i = 0; i < 8; i++) {
        int m = m0 + tx * 8 + i;
        if (m >= HW) continue;
        float* row = out + ((size_t)b * HW + m) * CMID + o0 + ty * 8;
#pragma unroll
        for (int j = 0; j < 4; j++) {
            float lo, hi;
            unpack2(acc2[i][j], lo, hi);
            float v0 = lo + b1[o0 + ty * 8 + j * 2];
            float v1 = hi + b1[o0 + ty * 8 + j * 2 + 1];
            float2 o;
            o.x = v0 > 0.f ? v0 : 0.f;
            o.y = v1 > 0.f ? v1 : 0.f;
            *reinterpret_cast<float2*>(row + j * 2) = o;
        }
    }
}

// ---------------- head ----------------
__global__ __launch_bounds__(64) void head_kernel(
    const float* __restrict__ t, const float* __restrict__ W2, const float* __restrict__ b2,
    const float* __restrict__ W3, const float* __restrict__ b3,
    float* __restrict__ boxes_all, u64* __restrict__ keys)
{
    const int pos = blockIdx.x;
    const int b = pos / HW;
    const int m = pos - b * HW;
    const int y = m / WW, x = m - y * WW;
    const int tid = threadIdx.x;

    __shared__ float tv[CMID];
    __shared__ float outv[48];

    const float* trow = t + (size_t)pos * CMID;
#pragma unroll
    for (int i = 0; i < 2; i++)
        reinterpret_cast<float4*>(tv)[tid + i * 64] =
            reinterpret_cast<const float4*>(trow)[tid + i * 64];
    __syncthreads();

    if (tid < 45) {
        const float* wr;
        float bias;
        if (tid < 36) { wr = W2 + (size_t)tid * CMID; bias = b2[tid]; }
        else          { wr = W3 + (size_t)(tid - 36) * CMID; bias = b3[tid - 36]; }
        float s0 = 0.f, s1 = 0.f, s2 = 0.f, s3 = 0.f;
        for (int j = 0; j < CMID; j += 4) {
            float4 tvv = *reinterpret_cast<const float4*>(&tv[j]);
            float4 wv = *reinterpret_cast<const float4*>(&wr[j]);
            s0 += tvv.x * wv.x; s1 += tvv.y * wv.y;
            s2 += tvv.z * wv.z; s3 += tvv.w * wv.w;
        }
        outv[tid] = ((s0 + s1) + (s2 + s3)) + bias;
    }
    __syncthreads();

    if (tid < NA) {
        const int a = tid;
        const double areas[3] = {16384.0, 65536.0, 262144.0};
        const double ratios[3] = {0.5, 1.0, 2.0};
        int ia = a / 3, ir = a - ia * 3;
        float w = (float)sqrt(areas[ia] * ratios[ir]);
        float h = (float)sqrt(areas[ia] / ratios[ir]);

        float tx_ = outv[a * 4 + 0];
        float ty_ = outv[a * 4 + 1];
        float clip = (float)log(62.5);
        float tw_ = fminf(outv[a * 4 + 2], clip);
        float th_ = fminf(outv[a * 4 + 3], clip);
        float logit = outv[36 + a];

        float cx = ((float)x + 0.5f) * 32.f;
        float cy = ((float)y + 0.5f) * 32.f;
        float x1 = cx - w * 0.5f, x2 = cx + w * 0.5f;
        float y1 = cy - h * 0.5f, y2 = cy + h * 0.5f;
        float wa = x2 - x1, ha = y2 - y1;
        float cxa = x1 + 0.5f * wa, cya = y1 + 0.5f * ha;

        float px = tx_ * wa + cxa;
        float py = ty_ * ha + cya;
        float pw = expf(tw_) * wa;
        float ph = expf(th_) * ha;

        float bx1 = fminf(fmaxf(px - pw * 0.5f, 0.f), 1600.f);
        float by1 = fminf(fmaxf(py - ph * 0.5f, 0.f), 1600.f);
        float bx2 = fminf(fmaxf(px + pw * 0.5f, 0.f), 1600.f);
        float by2 = fminf(fmaxf(py + ph * 0.5f, 0.f), 1600.f);

        float bw = bx2 - bx1, bh = by2 - by1;
        float score = 1.f / (1.f + expf(-logit));
        bool valid = (score >= 0.1f) && (bw > 16.f) && (bh > 16.f);
        float ms = valid ? score : -1.0f;

        int idx = m * NA + a;
        size_t bi = (size_t)b * NANCH + idx;
        boxes_all[bi * 4 + 0] = bx1;
        boxes_all[bi * 4 + 1] = by1;
        boxes_all[bi * 4 + 2] = bx2;
        boxes_all[bi * 4 + 3] = by2;
        keys[(size_t)b * SEG + idx] = ((u64)(~ordf(ms)) << 32) | (u32)idx;
    }
}

// ---------------- bitonic sort ----------------
__global__ __launch_bounds__(1024) void bsortA(u64* __restrict__ keys)
{
    __shared__ u64 s[4096];
    const int cb = blockIdx.x * 4096;
    const int segb = cb & (SEG - 1);
    const int tid = threadIdx.x;
#pragma unroll
    for (int i = 0; i < 4; i++) s[tid + i * 1024] = keys[cb + tid + i * 1024];
    __syncthreads();
    for (int size = 2; size <= 4096; size <<= 1) {
        for (int stride = size >> 1; stride >= 1; stride >>= 1) {
#pragma unroll 1
            for (int t = tid; t < 2048; t += 1024) {
                int l = ((t & ~(stride - 1)) << 1) | (t & (stride - 1));
                int r = l | stride;
                bool up = (((l + segb) & size) == 0);
                u64 a = s[l], bk = s[r];
                if ((a > bk) == up) { s[l] = bk; s[r] = a; }
            }
            __syncthreads();
        }
    }
#pragma unroll
    for (int i = 0; i < 4; i++) keys[cb + tid + i * 1024] = s[tid + i * 1024];
}

__global__ __launch_bounds__(256) void bsortG(u64* __restrict__ keys, int size, int stride)
{
    int t = blockIdx.x * blockDim.x + threadIdx.x;
    int l = ((t & ~(stride - 1)) << 1) | (t & (stride - 1));
    int r = l | stride;
    bool up = (((l & (SEG - 1)) & size) == 0);
    u64 a = keys[l], bk = keys[r];
    if ((a > bk) == up) { keys[l] = bk; keys[r] = a; }
}

__global__ __launch_bounds__(1024) void bsortF(u64* __restrict__ keys, int size)
{
    __shared__ u64 s[4096];
    const int cb = blockIdx.x * 4096;
    const int segb = cb & (SEG - 1);
    const int tid = threadIdx.x;
#pragma unroll
    for (int i = 0; i < 4; i++) s[tid + i * 1024] = keys[cb + tid + i * 1024];
    __syncthreads();
    const bool up = ((segb & size) == 0);
    for (int stride = 2048; stride >= 1; stride >>= 1) {
#pragma unroll 1
        for (int t = tid; t < 2048; t += 1024) {
            int l = ((t & ~(stride - 1)) << 1) | (t & (stride - 1));
            int r = l | stride;
            u64 a = s[l], bk = s[r];
            if ((a > bk) == up) { s[l] = bk; s[r] = a; }
        }
        __syncthreads();
    }
#pragma unroll
    for (int i = 0; i < 4; i++) keys[cb + tid + i * 1024] = s[tid + i * 1024];
}

// ---------------- gather top-2000 ----------------
__global__ __launch_bounds__(256) void gather_kernel(
    const u64* __restrict__ keys, const float* __restrict__ boxes_all,
    float* __restrict__ topboxes, float* __restrict__ topscores)
{
    int t = blockIdx.x * blockDim.x + threadIdx.x;
    if (t >= BATCH * PRE_N) return;
    int seg = t / PRE_N, r = t - seg * PRE_N;
    u64 key = keys[(size_t)seg * SEG + r];
    u32 idx = (u32)(key & 0xFFFFFFFFu);
    topscores[t] = unordf(~(u32)(key >> 32));
    float4 bb = *reinterpret_cast<const float4*>(boxes_all + ((size_t)seg * NANCH + idx) * 4);
    *reinterpret_cast<float4*>(topboxes + (size_t)t * 4) = bb;
}

// ---------------- NMS ----------------
__device__ __forceinline__ bool iou_gt(float4 bi, float area_i, float4 bj)
{
    float area_j = (bj.z - bj.x) * (bj.w - bj.y);
    float ltx = fmaxf(bi.x, bj.x), lty = fmaxf(bi.y, bj.y);
    float rbx = fminf(bi.z, bj.z), rby = fminf(bi.w, bj.w);
    float wx = fmaxf(rbx - ltx, 0.f), wy = fmaxf(rby - lty, 0.f);
    float inter = wx * wy;
    return inter / (area_i + area_j - inter + 1e-9f) > 0.7f;
}

__global__ __launch_bounds__(256) void mask_kernel(
    const float* __restrict__ topboxes, u64* __restrict__ masks)
{
    int row = blockIdx.x * 8 + (threadIdx.x >> 5);
    int lane = threadIdx.x & 31;
    int seg = row / PRE_N, i = row - seg * PRE_N;
    const float* B = topboxes + (size_t)seg * PRE_N * 4;
    float4 bi = *reinterpret_cast<const float4*>(B + (size_t)i * 4);
    float area_i = (bi.z - bi.x) * (bi.w - bi.y);
    u64* mrow = masks + (size_t)row * 32;
    for (int w = 0; w < 32; w++) {
        int j0 = w * 64;
        bool p0 = false, p1 = false;
        int j = j0 + lane;
        if (j < PRE_N && j > i)
            p0 = iou_gt(bi, area_i, *reinterpret_cast<const float4*>(B + (size_t)j * 4));
        j = j0 + 32 + lane;
        if (j < PRE_N && j > i)
            p1 = iou_gt(bi, area_i, *reinterpret_cast<const float4*>(B + (size_t)j * 4));
        u32 lo = __ballot_sync(0xFFFFFFFFu, p0);
        u32 hi = __ballot_sync(0xFFFFFFFFu, p1);
        if (lane == 0) mrow[w] = ((u64)hi << 32) | lo;
    }
}

__global__ __launch_bounds__(256) void scan_kernel(
    const float* __restrict__ topscores, const u64* __restrict__ masks, u64* __restrict__ keep)
{
    const int seg = blockIdx.x;
    __shared__ u64 buf[64 * 32];
    const int tid = threadIdx.x;
    const int lane = tid & 31, wid = tid >> 5;

    u64 keepw = 0;
    if (wid == 0) {
        for (int bbit = 0; bbit < 64; bbit++) {
            int i = lane * 64 + bbit;
            if (i < PRE_N && topscores[seg * PRE_N + i] > 0.f) keepw |= 1ULL << bbit;
        }
    }
    const u64* mseg = masks + (size_t)seg * PRE_N * 32;
    for (int c = 0; c < 32; c++) {
        __syncthreads();
        int r0 = c * 64;
        for (int e = tid; e < 64 * 32; e += 256) {
            int rr = e >> 5, wwi = e & 31;
            int row = r0 + rr;
            buf[e] = (row < PRE_N) ? mseg[(size_t)row * 32 + wwi] : 0ULL;
        }
        __syncthreads();
        if (wid == 0) {
            int n = PRE_N - r0; if (n > 64) n = 64;
            for (int r = 0; r < n; r++) {
                u64 kw = __shfl_sync(0xFFFFFFFFu, keepw, c);
                if ((kw >> r) & 1ULL) keepw &= ~buf[r * 32 + lane];
            }
        }
    }
    __syncthreads();
    if (wid == 0) keep[seg * 32 + lane] = keepw;
}

__global__ __launch_bounds__(1024) void post_kernel(
    const float* __restrict__ topscores, const float* __restrict__ topboxes,
    const u64* __restrict__ keepbits, float* __restrict__ out)
{
    const int seg = blockIdx.x;
    __shared__ u64 s[2048];
    const int tid = threadIdx.x;
    for (int i = tid; i < 2048; i += 1024) {
        u64 key;
        if (i < PRE_N) {
            float sc = topscores[seg * PRE_N + i];
            int kept = (int)((keepbits[seg * 32 + (i >> 6)] >> (i & 63)) & 1ULL);
            float ms = kept ? sc : -1.0f;
            key = ((u64)(~ordf(ms)) << 32) | (u32)i;
        } else key = ~0ULL;
        s[i] = key;
    }
    __syncthreads();
    for (int size = 2; size <= 2048; size <<= 1)
        for (int stride = size >> 1; stride >= 1; stride >>= 1) {
            int l = ((tid & ~(stride - 1)) << 1) | (tid & (stride - 1));
            int r = l | stride;
            bool up = ((l & size) == 0);
            u64 a = s[l], bk = s[r];
            if ((a > bk) == up) { s[l] = bk; s[r] = a; }
            __syncthreads();
        }
    if (tid < POST_N) {
        u64 key = s[tid];
        u32 idx = (u32)(key & 0xFFFFFFFFu);
        float sc = unordf(~(u32)(key >> 32));
        float4 bb = *reinterpret_cast<const float4*>(topboxes + ((size_t)seg * PRE_N + idx) * 4);
        float* ob = out + ((size_t)seg * POST_N + tid) * 4;
        ob[0] = bb.x; ob[1] = bb.y; ob[2] = bb.z; ob[3] = bb.w;
        out[BATCH * POST_N * 4 + seg * POST_N + tid] = sc;
    }
}

// ---------------- launch ----------------
extern "C" void kernel_launch(void* const* d_in, const int* in_sizes, int n_in,
                              void* d_out, int out_size)
{
    const float* feat = (const float*)d_in[0];
    const float* W1   = (const float*)d_in[1];
    const float* b1   = (const float*)d_in[2];
    const float* W2   = (const float*)d_in[3];
    const float* b2   = (const float*)d_in[4];
    const float* W3   = (const float*)d_in[5];
    const float* b3   = (const float*)d_in[6];
    float* out = (float*)d_out;

    float *t_ptr, *boxes_ptr, *tb_ptr, *ts_ptr;
    u64 *keys_ptr, *mask_ptr, *keep_ptr;
    cudaGetSymbolAddress((void**)&t_ptr, g_t);
    cudaGetSymbolAddress((void**)&boxes_ptr, g_boxes);
    cudaGetSymbolAddress((void**)&keys_ptr, g_keys);
    cudaGetSymbolAddress((void**)&tb_ptr, g_topboxes);
    cudaGetSymbolAddress((void**)&ts_ptr, g_topscores);
    cudaGetSymbolAddress((void**)&mask_ptr, g_mask);
    cudaGetSymbolAddress((void**)&keep_ptr, g_keep);

    // 1. conv + relu (fp32x2, TK=16, register prefetch, occ=2)
    dim3 cgrid((HW + TM - 1) / TM, CMID / TN, BATCH);   // 20 x 4 x 8 = 640 CTAs
    conv_kernel<<<cgrid, 256>>>(feat, W1, b1, t_ptr);

    // 2. pad keys then head
    cudaMemsetAsync(keys_ptr, 0xFF, (size_t)BATCH * SEG * sizeof(u64));
    head_kernel<<<BATCH * HW, 64>>>(t_ptr, W2, b2, W3, b3, boxes_ptr, keys_ptr);

    // 3. per-segment bitonic sort
    bsortA<<<BATCH * SEG / 4096, 1024>>>(keys_ptr);
    bsortG<<<512, 256>>>(keys_ptr, 8192, 4096);
    bsortF<<<BATCH * SEG / 4096, 1024>>>(keys_ptr, 8192);
    bsortG<<<512, 256>>>(keys_ptr, 16384, 8192);
    bsortG<<<512, 256>>>(keys_ptr, 16384, 4096);
    bsortF<<<BATCH * SEG / 4096, 1024>>>(keys_ptr, 16384);
    bsortG<<<512, 256>>>(keys_ptr, 32768, 16384);
    bsortG<<<512, 256>>>(keys_ptr, 32768, 8192);
    bsortG<<<512, 256>>>(keys_ptr, 32768, 4096);
    bsortF<<<BATCH * SEG / 4096, 1024>>>(keys_ptr, 32768);

    // 4-6. gather, NMS, output
    gather_kernel<<<(BATCH * PRE_N + 255) / 256, 256>>>(keys_ptr, boxes_ptr, tb_ptr, ts_ptr);
    mask_kernel<<<BATCH * PRE_N / 8, 256>>>(tb_ptr, mask_ptr);
    scan_kernel<<<BATCH, 256>>>(ts_ptr, mask_ptr, keep_ptr);
    post_kernel<<<BATCH, 1024>>>(ts_ptr, tb_ptr, keep_ptr, out);
}